// round 2
// baseline (speedup 1.0000x reference)
#include <cuda_runtime.h>
#include <math.h>

#define T_ 2048
#define H_ 2048
#define NH_ 16
#define NKV_ 4
#define DH_ 128
#define E_ 16
#define TOPK_ 2
#define I_ 1024
#define EPS_ 1e-6f

// ---------------- scratch (static device globals; no allocation allowed) ----------------
__device__ float g_cat[(size_t)T_ * 2 * H_];        // concat(rms(emb), rms(hid))
__device__ float g_x[(size_t)T_ * H_];              // x / residual2
__device__ float g_res[(size_t)T_ * H_];            // residual1
__device__ float g_xn[(size_t)T_ * H_];             // normalized x
__device__ float g_q[(size_t)T_ * NH_ * DH_];
__device__ float g_k[(size_t)T_ * NKV_ * DH_];
__device__ float g_v[(size_t)T_ * NKV_ * DH_];
__device__ float g_attn[(size_t)T_ * NH_ * DH_];
__device__ float g_gbuf[(size_t)T_ * TOPK_ * I_];   // gate proj -> silu*up
__device__ float g_ubuf[(size_t)T_ * TOPK_ * I_];   // up proj
__device__ float g_downbuf[(size_t)T_ * TOPK_ * H_];// down proj per slot (gate-scaled)
__device__ int   g_top_idx[T_ * TOPK_];
__device__ float g_top_w[T_ * TOPK_];
__device__ int   g_counts[E_];
__device__ int   g_counts2[E_];
__device__ int   g_offs[E_ + 1];
__device__ int   g_tok_of_slot[T_ * TOPK_];
__device__ float g_gate_of_slot[T_ * TOPK_];
__device__ int   g_slot_of_tok[T_ * TOPK_];

// ---------------- helpers ----------------
__device__ __forceinline__ float block_reduce_sum(float v) {
    __shared__ float sb[33];
    int tid = threadIdx.x;
#pragma unroll
    for (int o = 16; o > 0; o >>= 1) v += __shfl_xor_sync(0xffffffffu, v, o);
    if ((tid & 31) == 0) sb[tid >> 5] = v;
    __syncthreads();
    if (tid == 0) {
        float s = 0.f;
        int nw = (blockDim.x + 31) >> 5;
        for (int i = 0; i < nw; i++) s += sb[i];
        sb[32] = s;
    }
    __syncthreads();
    return sb[32];
}

// ---------------- generic tiled SGEMM ----------------
// C[M,N] = gather(A)[M,K] * B[K,N]  (+ addsrc) (* rowscale), optional dup write,
// optional per-expert segments (segoff) with B stride.
__global__ void gemm64(const float* __restrict__ A, const float* __restrict__ B,
                       float* __restrict__ C,
                       int M, int N, int Kd, int lda, int ldb, int ldc,
                       const int* __restrict__ rowmap,
                       const float* __restrict__ addsrc,
                       float* __restrict__ Cdup,
                       const int* __restrict__ segoff,
                       long long strideB,
                       const float* __restrict__ rowscale) {
    int row0 = 0, rowEnd = M;
    const float* Bp = B;
    if (segoff) {
        int e = blockIdx.z;
        row0 = segoff[e];
        rowEnd = segoff[e + 1];
        Bp = B + (long long)e * strideB;
    }
    int rbase = row0 + blockIdx.y * 64;
    if (rbase >= rowEnd) return;
    int cbase = blockIdx.x * 64;

    __shared__ float As[64][17];
    __shared__ __align__(16) float Bs[16][64];

    int tid = threadIdx.x;             // 256 threads
    int tx = tid & 15, ty = tid >> 4;

    float acc[4][4];
#pragma unroll
    for (int i = 0; i < 4; i++)
#pragma unroll
        for (int j = 0; j < 4; j++) acc[i][j] = 0.f;

    // A load map: row = tid/4, k-offset = (tid%4)*4
    int a_r = tid >> 2;
    int a_k = (tid & 3) * 4;
    int crowA = rbase + a_r;
    const float* Arow = nullptr;
    if (crowA < rowEnd) {
        int ar = rowmap ? rowmap[crowA] : crowA;
        Arow = A + (long long)ar * lda;
    }
    // B load map: k-row = tid/16, col = (tid%16)*4
    int b_k = tid >> 4;
    int b_c = (tid & 15) * 4;

    for (int k0 = 0; k0 < Kd; k0 += 16) {
        float4 av = make_float4(0.f, 0.f, 0.f, 0.f);
        if (Arow) av = *reinterpret_cast<const float4*>(Arow + k0 + a_k);
        float4 bv = *reinterpret_cast<const float4*>(
            Bp + (long long)(k0 + b_k) * ldb + cbase + b_c);
        __syncthreads();
        As[a_r][a_k + 0] = av.x;
        As[a_r][a_k + 1] = av.y;
        As[a_r][a_k + 2] = av.z;
        As[a_r][a_k + 3] = av.w;
        *reinterpret_cast<float4*>(&Bs[b_k][b_c]) = bv;
        __syncthreads();
#pragma unroll
        for (int kk = 0; kk < 16; kk++) {
            float a0 = As[ty * 4 + 0][kk];
            float a1 = As[ty * 4 + 1][kk];
            float a2 = As[ty * 4 + 2][kk];
            float a3 = As[ty * 4 + 3][kk];
            float4 b = *reinterpret_cast<const float4*>(&Bs[kk][tx * 4]);
            acc[0][0] += a0 * b.x; acc[0][1] += a0 * b.y; acc[0][2] += a0 * b.z; acc[0][3] += a0 * b.w;
            acc[1][0] += a1 * b.x; acc[1][1] += a1 * b.y; acc[1][2] += a1 * b.z; acc[1][3] += a1 * b.w;
            acc[2][0] += a2 * b.x; acc[2][1] += a2 * b.y; acc[2][2] += a2 * b.z; acc[2][3] += a2 * b.w;
            acc[3][0] += a3 * b.x; acc[3][1] += a3 * b.y; acc[3][2] += a3 * b.z; acc[3][3] += a3 * b.w;
        }
    }
#pragma unroll
    for (int i = 0; i < 4; i++) {
        int r = rbase + ty * 4 + i;
        if (r >= rowEnd) break;
        float sc = rowscale ? rowscale[r] : 1.f;
#pragma unroll
        for (int j = 0; j < 4; j++) {
            int c = cbase + tx * 4 + j;
            float v = acc[i][j] * sc;
            if (addsrc) v += addsrc[(long long)r * ldc + c];
            C[(long long)r * ldc + c] = v;
            if (Cdup) Cdup[(long long)r * ldc + c] = v;
        }
    }
}

// ---------------- embed lookup + rms -> concat ----------------
__global__ void embcat_kernel(const int* __restrict__ ids,
                              const float* __restrict__ emb_w,
                              const float* __restrict__ hid,
                              const float* __restrict__ we,
                              const float* __restrict__ wh) {
    int t = blockIdx.x;
    const float* er = emb_w + (size_t)ids[t] * H_;
    const float* hr = hid + (size_t)t * H_;
    float ss = 0.f;
    for (int h = threadIdx.x; h < H_; h += blockDim.x) { float v = er[h]; ss += v * v; }
    float tot = block_reduce_sum(ss);
    float rs = rsqrtf(tot / H_ + EPS_);
    for (int h = threadIdx.x; h < H_; h += blockDim.x)
        g_cat[(size_t)t * 2 * H_ + h] = er[h] * rs * (1.f + we[h]);
    ss = 0.f;
    for (int h = threadIdx.x; h < H_; h += blockDim.x) { float v = hr[h]; ss += v * v; }
    tot = block_reduce_sum(ss);
    rs = rsqrtf(tot / H_ + EPS_);
    for (int h = threadIdx.x; h < H_; h += blockDim.x)
        g_cat[(size_t)t * 2 * H_ + H_ + h] = hr[h] * rs * (1.f + wh[h]);
}

// ---------------- row RMS norm ----------------
__global__ void rmsnorm_kernel(const float* __restrict__ in,
                               const float* __restrict__ w,
                               float* __restrict__ out) {
    int t = blockIdx.x;
    const float* r = in + (size_t)t * H_;
    float ss = 0.f;
    for (int h = threadIdx.x; h < H_; h += blockDim.x) { float v = r[h]; ss += v * v; }
    float tot = block_reduce_sum(ss);
    float rs = rsqrtf(tot / H_ + EPS_);
    for (int h = threadIdx.x; h < H_; h += blockDim.x)
        out[(size_t)t * H_ + h] = r[h] * rs * (1.f + w[h]);
}

// ---------------- per-head rms + rope (in place), 128 threads ----------------
__global__ void qkrope_kernel(float* __restrict__ x, int nheads,
                              const float* __restrict__ nw,
                              const int* __restrict__ positions) {
    int t = blockIdx.x, h = blockIdx.y;
    float* v = x + ((size_t)t * nheads + h) * DH_;
    int d = threadIdx.x;  // 0..127
    float val = v[d];
    float ss = val * val;
#pragma unroll
    for (int o = 16; o > 0; o >>= 1) ss += __shfl_xor_sync(0xffffffffu, ss, o);
    __shared__ float ws[4];
    if ((d & 31) == 0) ws[d >> 5] = ss;
    __syncthreads();
    float tot = ws[0] + ws[1] + ws[2] + ws[3];
    float rs = rsqrtf(tot / DH_ + EPS_);
    float n = val * rs * (1.f + nw[d]);
    __shared__ float nv[DH_];
    nv[d] = n;
    __syncthreads();
    int pos = positions[t];
    int i = d & 63;
    float inv = expf(-((float)i / 64.f) * 13.815510557964274f);  // 1e6^(-i/64)
    float ang = (float)pos * inv;
    float c = cosf(ang), s = sinf(ang);
    float outv;
    if (d < 64) outv = nv[d] * c - nv[d + 64] * s;
    else        outv = nv[d] * c + nv[d - 64] * s;
    v[d] = outv;
}

// ---------------- flash attention (causal, GQA) ----------------
// block = (q_tile of 32, head). 128 threads: qr = tid>>2, quad = tid&3 owns 32 dims.
__global__ void attn_kernel(const int* __restrict__ positions) {
    int qt = blockIdx.x, h = blockIdx.y;
    int tid = threadIdx.x;
    int qr = tid >> 2, quad = tid & 3;
    int qrow = qt * 32 + qr;
    int kvh = h >> 2;  // NH/NKV = 4

    __shared__ __align__(16) float4 Ks[32][32];
    __shared__ __align__(16) float4 Vs[32][32];
    __shared__ float S[32][33];
    __shared__ float mrow[32], lrow[32], arow[32];
    __shared__ int kpos_s[32];

    float4 qv[8];
    const float* qp = g_q + ((size_t)qrow * NH_ + h) * DH_ + quad * 32;
#pragma unroll
    for (int i = 0; i < 8; i++) qv[i] = *reinterpret_cast<const float4*>(qp + i * 4);

    if (quad == 0) { mrow[qr] = -1e30f; lrow[qr] = 0.f; }
    float acc[32];
#pragma unroll
    for (int i = 0; i < 32; i++) acc[i] = 0.f;
    int qpos = positions[qrow];
    const float scale = 0.08838834764831845f;  // 1/sqrt(128)

    for (int kt = 0; kt <= qt; kt++) {
        __syncthreads();
        for (int ii = tid; ii < 32 * 32; ii += 128) {
            int kr = ii >> 5, c = ii & 31;
            size_t base = ((size_t)(kt * 32 + kr) * NKV_ + kvh) * DH_;
            Ks[kr][c] = *reinterpret_cast<const float4*>(g_k + base + c * 4);
            Vs[kr][c] = *reinterpret_cast<const float4*>(g_v + base + c * 4);
        }
        if (tid < 32) kpos_s[tid] = positions[kt * 32 + tid];
        __syncthreads();
        // scores
        for (int kr = 0; kr < 32; kr++) {
            float p = 0.f;
#pragma unroll
            for (int i = 0; i < 8; i++) {
                float4 kk = Ks[kr][quad * 8 + i];
                p += qv[i].x * kk.x + qv[i].y * kk.y + qv[i].z * kk.z + qv[i].w * kk.w;
            }
            p += __shfl_xor_sync(0xffffffffu, p, 1);
            p += __shfl_xor_sync(0xffffffffu, p, 2);
            if (quad == 0)
                S[qr][kr] = (kpos_s[kr] <= qpos) ? p * scale : -1e30f;
        }
        __syncthreads();
        // online softmax row update
        if (tid < 32) {
            int r = tid;
            float mold = mrow[r], mx = mold;
            for (int kr = 0; kr < 32; kr++) mx = fmaxf(mx, S[r][kr]);
            float al = expf(mold - mx);
            float rsum = 0.f;
            for (int kr = 0; kr < 32; kr++) {
                float pe = expf(S[r][kr] - mx);
                S[r][kr] = pe;
                rsum += pe;
            }
            mrow[r] = mx;
            lrow[r] = lrow[r] * al + rsum;
            arow[r] = al;
        }
        __syncthreads();
        float al = arow[qr];
#pragma unroll
        for (int i = 0; i < 32; i++) acc[i] *= al;
        for (int kr = 0; kr < 32; kr++) {
            float w = S[qr][kr];
#pragma unroll
            for (int i = 0; i < 8; i++) {
                float4 vv = Vs[kr][quad * 8 + i];
                acc[i * 4 + 0] += w * vv.x;
                acc[i * 4 + 1] += w * vv.y;
                acc[i * 4 + 2] += w * vv.z;
                acc[i * 4 + 3] += w * vv.w;
            }
        }
    }
    float inv_l = 1.f / lrow[qr];
    float* orow = g_attn + (size_t)qrow * (NH_ * DH_) + h * DH_ + quad * 32;
#pragma unroll
    for (int i = 0; i < 8; i++) {
        float4 o = make_float4(acc[i * 4 + 0] * inv_l, acc[i * 4 + 1] * inv_l,
                               acc[i * 4 + 2] * inv_l, acc[i * 4 + 3] * inv_l);
        *reinterpret_cast<float4*>(orow + i * 4) = o;
    }
}

// ---------------- router: logits, softmax, top-2, counts ----------------
__global__ void zero_counts_kernel() {
    if (threadIdx.x < E_) g_counts[threadIdx.x] = 0;
}

__global__ void router_kernel(const float* __restrict__ rw) {
    int t = blockIdx.x;
    __shared__ float part[256];
    __shared__ float logits[E_];
    int tid = threadIdx.x;
    int e = tid >> 4, c = tid & 15;
    float s = 0.f;
    const float* xr = g_xn + (size_t)t * H_;
    for (int h = c * 128; h < (c + 1) * 128; h++) s += xr[h] * rw[(size_t)h * E_ + e];
    part[tid] = s;
    __syncthreads();
    if (c == 0) {
        float tot = 0.f;
        for (int i = 0; i < 16; i++) tot += part[e * 16 + i];
        logits[e] = tot;
    }
    __syncthreads();
    if (tid == 0) {
        float mx = -1e30f;
        for (int i = 0; i < E_; i++) mx = fmaxf(mx, logits[i]);
        float p[E_];
        for (int i = 0; i < E_; i++) p[i] = expf(logits[i] - mx);
        int i0 = 0; float v0 = p[0];
        for (int i = 1; i < E_; i++) if (p[i] > v0) { v0 = p[i]; i0 = i; }
        int i1 = -1; float v1 = -1.f;
        for (int i = 0; i < E_; i++) if (i != i0 && p[i] > v1) { v1 = p[i]; i1 = i; }
        float denom = v0 + v1;
        g_top_idx[t * 2 + 0] = i0;
        g_top_idx[t * 2 + 1] = i1;
        g_top_w[t * 2 + 0] = v0 / denom;
        g_top_w[t * 2 + 1] = v1 / denom;
        atomicAdd(&g_counts[i0], 1);
        atomicAdd(&g_counts[i1], 1);
    }
}

__global__ void offsets_kernel() {
    if (threadIdx.x == 0) {
        int acc = 0;
        for (int e = 0; e < E_; e++) { g_offs[e] = acc; acc += g_counts[e]; }
        g_offs[E_] = acc;
    }
    if (threadIdx.x < E_) g_counts2[threadIdx.x] = 0;
}

__global__ void scatter_kernel() {
    int t = blockIdx.x * blockDim.x + threadIdx.x;
    if (t >= T_) return;
    for (int k = 0; k < TOPK_; k++) {
        int e = g_top_idx[t * 2 + k];
        int pos = atomicAdd(&g_counts2[e], 1);
        int slot = g_offs[e] + pos;
        g_tok_of_slot[slot] = t;
        g_gate_of_slot[slot] = g_top_w[t * 2 + k];
        g_slot_of_tok[t * 2 + k] = slot;
    }
}

// ---------------- silu(g)*u in place ----------------
__global__ void silu_mul_kernel() {
    size_t i = (size_t)blockIdx.x * blockDim.x + threadIdx.x;
    if (i >= (size_t)T_ * TOPK_ * I_) return;
    float x = g_gbuf[i];
    g_gbuf[i] = (x / (1.f + expf(-x))) * g_ubuf[i];
}

// ---------------- final combine + rms ----------------
__global__ void final_kernel(const float* __restrict__ fw, float* __restrict__ out) {
    int t = blockIdx.x;
    __shared__ float buf[H_];
    int s0 = g_slot_of_tok[t * 2 + 0];
    int s1 = g_slot_of_tok[t * 2 + 1];
    float ss = 0.f;
    for (int h = threadIdx.x; h < H_; h += blockDim.x) {
        float v = g_x[(size_t)t * H_ + h] + g_downbuf[(size_t)s0 * H_ + h] +
                  g_downbuf[(size_t)s1 * H_ + h];
        buf[h] = v;
        ss += v * v;
    }
    float tot = block_reduce_sum(ss);
    float rs = rsqrtf(tot / H_ + EPS_);
    for (int h = threadIdx.x; h < H_; h += blockDim.x)
        out[(size_t)t * H_ + h] = buf[h] * rs * (1.f + fw[h]);
}

// ---------------- launch ----------------
extern "C" void kernel_launch(void* const* d_in, const int* in_sizes, int n_in,
                              void* d_out, int out_size) {
    const int* input_ids      = (const int*)d_in[0];
    const int* positions      = (const int*)d_in[1];
    const float* hidden       = (const float*)d_in[2];
    // d_in[3] = spec_step_idx (unused)
    const float* embed_w      = (const float*)d_in[4];
    const float* fc_w         = (const float*)d_in[5];
    const float* pre_fc_emb_w = (const float*)d_in[6];
    const float* pre_fc_hid_w = (const float*)d_in[7];
    const float* in_ln_w      = (const float*)d_in[8];
    const float* post_ln_w    = (const float*)d_in[9];
    const float* final_norm_w = (const float*)d_in[10];
    const float* wq           = (const float*)d_in[11];
    const float* wk           = (const float*)d_in[12];
    const float* wv           = (const float*)d_in[13];
    const float* wo           = (const float*)d_in[14];
    const float* q_norm_w     = (const float*)d_in[15];
    const float* k_norm_w     = (const float*)d_in[16];
    const float* router_w     = (const float*)d_in[17];
    const float* w_gate       = (const float*)d_in[18];
    const float* w_up         = (const float*)d_in[19];
    const float* w_down       = (const float*)d_in[20];
    float* out = (float*)d_out;

    float *p_cat, *p_x, *p_res, *p_xn, *p_q, *p_k, *p_v, *p_attn, *p_g, *p_u, *p_down, *p_gate;
    int *p_tok, *p_offs;
    cudaGetSymbolAddress((void**)&p_cat, g_cat);
    cudaGetSymbolAddress((void**)&p_x, g_x);
    cudaGetSymbolAddress((void**)&p_res, g_res);
    cudaGetSymbolAddress((void**)&p_xn, g_xn);
    cudaGetSymbolAddress((void**)&p_q, g_q);
    cudaGetSymbolAddress((void**)&p_k, g_k);
    cudaGetSymbolAddress((void**)&p_v, g_v);
    cudaGetSymbolAddress((void**)&p_attn, g_attn);
    cudaGetSymbolAddress((void**)&p_g, g_gbuf);
    cudaGetSymbolAddress((void**)&p_u, g_ubuf);
    cudaGetSymbolAddress((void**)&p_down, g_downbuf);
    cudaGetSymbolAddress((void**)&p_gate, g_gate_of_slot);
    cudaGetSymbolAddress((void**)&p_tok, g_tok_of_slot);
    cudaGetSymbolAddress((void**)&p_offs, g_offs);

    // 1. embed + rms -> concat
    embcat_kernel<<<T_, 256>>>(input_ids, embed_w, hidden, pre_fc_emb_w, pre_fc_hid_w);

    // 2. fc: x = cat @ fc_w ; residual = x
    gemm64<<<dim3(H_ / 64, T_ / 64), 256>>>(p_cat, fc_w, p_x, T_, H_, 2 * H_,
                                            2 * H_, H_, H_, nullptr, nullptr, p_res,
                                            nullptr, 0, nullptr);

    // 3. in_ln
    rmsnorm_kernel<<<T_, 256>>>(p_x, in_ln_w, p_xn);

    // 4. qkv
    gemm64<<<dim3((NH_ * DH_) / 64, T_ / 64), 256>>>(p_xn, wq, p_q, T_, NH_ * DH_, H_,
                                                     H_, NH_ * DH_, NH_ * DH_,
                                                     nullptr, nullptr, nullptr, nullptr, 0, nullptr);
    gemm64<<<dim3((NKV_ * DH_) / 64, T_ / 64), 256>>>(p_xn, wk, p_k, T_, NKV_ * DH_, H_,
                                                      H_, NKV_ * DH_, NKV_ * DH_,
                                                      nullptr, nullptr, nullptr, nullptr, 0, nullptr);
    gemm64<<<dim3((NKV_ * DH_) / 64, T_ / 64), 256>>>(p_xn, wv, p_v, T_, NKV_ * DH_, H_,
                                                      H_, NKV_ * DH_, NKV_ * DH_,
                                                      nullptr, nullptr, nullptr, nullptr, 0, nullptr);

    // 5. q/k norm + rope
    qkrope_kernel<<<dim3(T_, NH_), DH_>>>(p_q, NH_, q_norm_w, positions);
    qkrope_kernel<<<dim3(T_, NKV_), DH_>>>(p_k, NKV_, k_norm_w, positions);

    // 6. attention
    attn_kernel<<<dim3(T_ / 32, NH_), 128>>>(positions);

    // 7. wo + residual -> x (this is residual2)
    gemm64<<<dim3(H_ / 64, T_ / 64), 256>>>(p_attn, wo, p_x, T_, H_, NH_ * DH_,
                                            NH_ * DH_, H_, H_, nullptr, p_res, nullptr,
                                            nullptr, 0, nullptr);

    // 8. post_ln
    rmsnorm_kernel<<<T_, 256>>>(p_x, post_ln_w, p_xn);

    // 9. router + bucketing
    zero_counts_kernel<<<1, 32>>>();
    router_kernel<<<T_, 256>>>(router_w);
    offsets_kernel<<<1, 32>>>();
    scatter_kernel<<<(T_ + 255) / 256, 256>>>();

    // 10. MoE grouped GEMMs
    gemm64<<<dim3(I_ / 64, T_ / 64, E_), 256>>>(p_xn, w_gate, p_g, 0, I_, H_,
                                                H_, I_, I_, p_tok, nullptr, nullptr,
                                                p_offs, (long long)H_ * I_, nullptr);
    gemm64<<<dim3(I_ / 64, T_ / 64, E_), 256>>>(p_xn, w_up, p_u, 0, I_, H_,
                                                H_, I_, I_, p_tok, nullptr, nullptr,
                                                p_offs, (long long)H_ * I_, nullptr);
    silu_mul_kernel<<<((size_t)T_ * TOPK_ * I_ + 255) / 256, 256>>>();
    gemm64<<<dim3(H_ / 64, T_ / 64, E_), 256>>>(p_g, w_down, p_down, 0, H_, I_,
                                                I_, H_, H_, nullptr, nullptr, nullptr,
                                                p_offs, (long long)I_ * H_, p_gate);

    // 11. combine + final rms
    final_kernel<<<T_, 256>>>(final_norm_w, out);
}